// round 7
// baseline (speedup 1.0000x reference)
#include <cuda_runtime.h>
#include <math.h>

// FeatureNormMagOnline — chunked-scan decomposition, round 3.
// EMA s_t = (1-a)*s_{t-1} + a*p_t over a chunk of length L:
//   s_end = (1-a)^L * s_start + c_chunk
// Pass 1: per-(seq,chunk) partial c from zero start (chunks 0..NCH-2 only;
//         the last chunk's partial is never consumed).
// Pass 2: reconstruct exact chunk-start state from partials (<=24 fma),
//         rescan chunk, write normalized output. Input re-read hits L2.
// Scheduling: dense 1 thread = 1 (bc,ch,f) item, 128-thread blocks,
// launch_bounds(128,11) -> pass2's 1607 blocks fit in ONE resident wave.

#define B_ 16
#define C_ 2
#define T_ 1000
#define F_ 257
#define BC_ (B_ * C_)      // 32
#define NCH 25
#define LCH 40             // NCH * LCH == T_
#define NCHP (NCH - 1)     // chunks needing partials

static const long long RES_ELEMS = (long long)B_ * C_ * T_ * F_ * 2;  // 16,448,000
static const int NSEQ  = BC_ * F_;              // 8224
static const int NIT1  = BC_ * NCHP * F_;       // 197,376 pass-1 items
static const int NIT2  = BC_ * NCH  * F_;       // 205,600 pass-2 items

// scratch: per-chunk partial EMA sums, layout c[ch][bc][f] for coalesced access
__device__ float g_c[NCHP * BC_ * F_];

__global__ void __launch_bounds__(128, 11)
pass1_partials(const float* __restrict__ in,
               const float* __restrict__ alpha)
{
    int w = blockIdx.x * 128 + threadIdx.x;
    if (w >= NIT1) return;
    int f  = w % F_;
    int sc = w / F_;
    int ch = sc % NCHP;
    int bc = sc / NCHP;
    int c  = bc % C_;

    float a   = 1.0f / (1.0f + __expf(-alpha[c * F_ + f]));
    float oma = 1.0f - a;

    const float2* __restrict__ inp =
        (const float2*)in + ((size_t)bc * T_ + (size_t)ch * LCH) * F_ + f;

    float s = 0.0f;
    #pragma unroll
    for (int tb = 0; tb < LCH; tb += 8) {
        float2 x[8];
        #pragma unroll
        for (int k = 0; k < 8; ++k)              // 8 independent loads in flight
            x[k] = inp[(size_t)(tb + k) * F_];
        #pragma unroll
        for (int k = 0; k < 8; ++k) {
            float p = fmaf(x[k].x, x[k].x, x[k].y * x[k].y);
            s = fmaf(oma, s, a * p);
        }
    }
    g_c[(ch * BC_ + bc) * F_ + f] = s;
}

__global__ void __launch_bounds__(128, 11)
pass2_scan_out(const float* __restrict__ in,
               const float* __restrict__ weights,
               const float* __restrict__ bias,
               const float* __restrict__ alpha,
               const float* __restrict__ s1,
               float* __restrict__ out,
               float* __restrict__ s_last_out)
{
    int w = blockIdx.x * 128 + threadIdx.x;
    if (w >= NIT2) return;
    int f  = w % F_;
    int sc = w / F_;
    int ch = sc % NCH;
    int bc = sc / NCH;
    int c  = bc % C_;
    int cf = c * F_ + f;

    float a   = 1.0f / (1.0f + __expf(-alpha[cf]));
    float oma = 1.0f - a;
    float wgt = weights[cf];
    float bb  = bias[cf];

    // reconstruct exact start state for this chunk from the partials
    float s = s1[bc * F_ + f];
    float omaL = powf(oma, (float)LCH);
    for (int i = 0; i < ch; ++i)
        s = fmaf(omaL, s, g_c[(i * BC_ + bc) * F_ + f]);

    const float2* __restrict__ inp =
        (const float2*)in + ((size_t)bc * T_ + (size_t)ch * LCH) * F_ + f;
    float2* __restrict__ outp =
        (float2*)out      + ((size_t)bc * T_ + (size_t)ch * LCH) * F_ + f;

    #pragma unroll
    for (int tb = 0; tb < LCH; tb += 8) {
        float2 x[8];
        #pragma unroll
        for (int k = 0; k < 8; ++k)
            x[k] = inp[(size_t)(tb + k) * F_];
        float2 o[8];
        #pragma unroll
        for (int k = 0; k < 8; ++k) {
            float p = fmaf(x[k].x, x[k].x, x[k].y * x[k].y);
            s = fmaf(oma, s, a * p);
            float inv = __fdividef(wgt, sqrtf(s) + 1e-8f);
            o[k].x = fmaf(x[k].x, inv, bb);
            o[k].y = fmaf(x[k].y, inv, bb);
        }
        #pragma unroll
        for (int k = 0; k < 8; ++k)
            __stcs(outp + (size_t)(tb + k) * F_, o[k]);
    }

    if (ch == NCH - 1 && s_last_out)
        s_last_out[bc * F_ + f] = s;
}

extern "C" void kernel_launch(void* const* d_in, const int* in_sizes, int n_in,
                              void* d_out, int out_size)
{
    const float* in      = (const float*)d_in[0];
    const float* weights = (const float*)d_in[1];
    const float* bias    = (const float*)d_in[2];
    const float* alpha   = (const float*)d_in[3];
    const float* s1      = (const float*)d_in[4];

    float* out = (float*)d_out;
    float* s_last = nullptr;
    if ((long long)out_size >= RES_ELEMS + NSEQ)
        s_last = out + RES_ELEMS;

    int g1 = (NIT1 + 127) / 128;   // 1542 blocks
    int g2 = (NIT2 + 127) / 128;   // 1607 blocks -> ~single resident wave

    pass1_partials<<<g1, 128>>>(in, alpha);
    pass2_scan_out<<<g2, 128>>>(in, weights, bias, alpha, s1, out, s_last);
}